// round 14
// baseline (speedup 1.0000x reference)
#include <cuda_runtime.h>
#include <cuda_fp16.h>

#define NU 100000
#define NP 50000
#define NE 2000000
#define NLAB 500000
#define HD 64

// ---------------- device scratch ----------------
__device__ int g_deg_p[NP];
__device__ int g_deg_u[NU];
__device__ int g_off_p[NP];
__device__ int g_off_u[NU];
__device__ int g_cur_p[NP];
__device__ int g_cur_u[NU];
__device__ __align__(16) int g_csr_src[NE];
__device__ __align__(16) int g_csr_dst[NE];
__device__ __align__(16) __half g_tu[NU * HD];    // fp16 message buffers
__device__ __align__(16) __half g_tp[NP * HD];
__device__ __align__(16) __half g_tu2[NU * HD];
__device__ __align__(16) __half g_tp2[NP * HD];
__device__ __align__(16) __half g_cu[NU * HD];    // fp16 final embeddings (classifier input)
__device__ __align__(16) __half g_cp[NP * HD];
__device__ __align__(16) float g_hu[NU * HD];
__device__ __align__(16) float g_hp[NP * HD];
__device__ __align__(16) float g_hu2[NU * HD];
__device__ __align__(16) float g_hp2[NP * HD];
__device__ int g_bsum_p[128];
__device__ int g_bsum_u[128];

// ---------------- CSR build (per side) ----------------
__global__ void k_zero_side(int* __restrict__ deg, int* __restrict__ cur, int n) {
    int i = blockIdx.x * blockDim.x + threadIdx.x;
    if (i < n) { deg[i] = 0; cur[i] = 0; }
}

__global__ void k_degree_side(const int* __restrict__ key, int* __restrict__ deg) {
    int i = blockIdx.x * blockDim.x + threadIdx.x;
    if (i < NE) atomicAdd(&deg[key[i]], 1);
}

__global__ void k_scan1(const int* __restrict__ deg, int n, int* __restrict__ out, int* __restrict__ bsums) {
    __shared__ int s[1024];
    int tid = threadIdx.x;
    int i = blockIdx.x * 1024 + tid;
    int v = (i < n) ? deg[i] : 0;
    s[tid] = v;
    __syncthreads();
    #pragma unroll
    for (int o = 1; o < 1024; o <<= 1) {
        int t = 0;
        if (tid >= o) t = s[tid - o];
        __syncthreads();
        s[tid] += t;
        __syncthreads();
    }
    if (i < n) out[i] = s[tid] - v;
    if (tid == 1023) bsums[blockIdx.x] = s[1023];
}

__global__ void k_scan2(int* __restrict__ bsums, int nb) {
    __shared__ int s[1024];
    int tid = threadIdx.x;
    int v = (tid < nb) ? bsums[tid] : 0;
    s[tid] = v;
    __syncthreads();
    #pragma unroll
    for (int o = 1; o < 1024; o <<= 1) {
        int t = 0;
        if (tid >= o) t = s[tid - o];
        __syncthreads();
        s[tid] += t;
        __syncthreads();
    }
    if (tid < nb) bsums[tid] = s[tid] - v;
}

__global__ void k_scan3(int* __restrict__ out, int n, const int* __restrict__ bsums) {
    int i = blockIdx.x * 1024 + threadIdx.x;
    if (i < n) out[i] += bsums[blockIdx.x];
}

__global__ void k_fill_side(const int* __restrict__ key, const int* __restrict__ val,
                            const int* __restrict__ off, int* __restrict__ cur,
                            int* __restrict__ csr) {
    int i = blockIdx.x * blockDim.x + threadIdx.x;
    if (i < NE) {
        int k = key[i];
        int slot = atomicAdd(&cur[k], 1);
        csr[off[k] + slot] = val[i];
    }
}

// ---------------- fused dual GEMM: outa(half) = x@Wa, outb(f32) = x@Wb + bb ----------------
template <int DIN>
__global__ __launch_bounds__(256) void k_gemm2(const float* __restrict__ x,
                                               const float* __restrict__ Wa,
                                               const float* __restrict__ Wb,
                                               const float* __restrict__ bb,
                                               __half* __restrict__ outa,
                                               float* __restrict__ outb, int n) {
    extern __shared__ float sm[];
    float* Was = sm;
    float* Wbs = sm + DIN * 64;
    float* xs  = sm + DIN * 128;
    int tid = threadIdx.x;
    int row0 = blockIdx.x * 32;

    for (int i = tid; i < DIN * 64; i += 256) { Was[i] = Wa[i]; Wbs[i] = Wb[i]; }
    for (int i = tid; i < 32 * DIN; i += 256) {
        int r = i / DIN, c = i % DIN;
        int row = row0 + r;
        xs[i] = (row < n) ? x[row * DIN + c] : 0.f;
    }
    __syncthreads();

    int col = tid & 63;
    int g = tid >> 6;
    const float* xbase = xs + (g * 8) * DIN;

    float bv = bb[col];
    float ta[8], tb[8];
    #pragma unroll
    for (int j = 0; j < 8; j++) { ta[j] = 0.f; tb[j] = bv; }

    #pragma unroll 4
    for (int k = 0; k < DIN; k += 4) {
        float wa0 = Was[(k + 0) * 64 + col];
        float wa1 = Was[(k + 1) * 64 + col];
        float wa2 = Was[(k + 2) * 64 + col];
        float wa3 = Was[(k + 3) * 64 + col];
        float wb0 = Wbs[(k + 0) * 64 + col];
        float wb1 = Wbs[(k + 1) * 64 + col];
        float wb2 = Wbs[(k + 2) * 64 + col];
        float wb3 = Wbs[(k + 3) * 64 + col];
        #pragma unroll
        for (int j = 0; j < 8; j++) {
            float4 xv = *(const float4*)&xbase[j * DIN + k];
            ta[j] = fmaf(xv.x, wa0, ta[j]); ta[j] = fmaf(xv.y, wa1, ta[j]);
            ta[j] = fmaf(xv.z, wa2, ta[j]); ta[j] = fmaf(xv.w, wa3, ta[j]);
            tb[j] = fmaf(xv.x, wb0, tb[j]); tb[j] = fmaf(xv.y, wb1, tb[j]);
            tb[j] = fmaf(xv.z, wb2, tb[j]); tb[j] = fmaf(xv.w, wb3, tb[j]);
        }
    }

    #pragma unroll
    for (int j = 0; j < 8; j++) {
        int row = row0 + g * 8 + j;
        if (row < n) {
            outa[row * 64 + col] = __float2half_rn(ta[j]);
            outb[row * 64 + col] = tb[j];
        }
    }
}

// ---------------- aggregation: warp per node, 4 edges in flight ----------------
// lanes split into 4 groups of 8; group handles one edge, lane covers 16B (8 halves).
// H16OUT: write fp16 rows to hout16 (classifier path) instead of fp32 in-place.
template <bool RELU, bool H16OUT>
__global__ __launch_bounds__(256) void k_agg(const __half* __restrict__ t,
                                             const int* __restrict__ csr,
                                             const int* __restrict__ off,
                                             const int* __restrict__ deg,
                                             float* __restrict__ h,
                                             __half* __restrict__ hout16, int n) {
    int warp = (blockIdx.x * blockDim.x + threadIdx.x) >> 5;
    int lane = threadIdx.x & 31;
    if (warp >= n) return;
    int start = off[warp];
    int d = deg[warp];
    int grp = lane >> 3;      // 0..3: edge group
    int l8 = lane & 7;        // 16B chunk of the 128B row

    float a0 = 0.f, a1 = 0.f, a2 = 0.f, a3 = 0.f;
    float a4 = 0.f, a5 = 0.f, a6 = 0.f, a7 = 0.f;
    for (int e = grp; e < d; e += 4) {
        int s = __ldg(&csr[start + e]);
        uint4 r = *(const uint4*)(t + (size_t)s * 64 + l8 * 8);
        float2 f0 = __half22float2(*(const __half2*)&r.x);
        float2 f1 = __half22float2(*(const __half2*)&r.y);
        float2 f2 = __half22float2(*(const __half2*)&r.z);
        float2 f3 = __half22float2(*(const __half2*)&r.w);
        a0 += f0.x; a1 += f0.y; a2 += f1.x; a3 += f1.y;
        a4 += f2.x; a5 += f2.y; a6 += f3.x; a7 += f3.y;
    }
    // combine the 4 edge groups (lanes l8, l8+8, l8+16, l8+24)
    #pragma unroll
    for (int o = 16; o >= 8; o >>= 1) {
        a0 += __shfl_down_sync(0xffffffffu, a0, o);
        a1 += __shfl_down_sync(0xffffffffu, a1, o);
        a2 += __shfl_down_sync(0xffffffffu, a2, o);
        a3 += __shfl_down_sync(0xffffffffu, a3, o);
        a4 += __shfl_down_sync(0xffffffffu, a4, o);
        a5 += __shfl_down_sync(0xffffffffu, a5, o);
        a6 += __shfl_down_sync(0xffffffffu, a6, o);
        a7 += __shfl_down_sync(0xffffffffu, a7, o);
    }

    if (lane < 8) {
        float inv = 1.0f / (float)((d > 1) ? d : 1);
        size_t base = (size_t)warp * 64 + l8 * 8;
        float4 s0 = *(const float4*)&h[base];
        float4 s1 = *(const float4*)&h[base + 4];
        float o0 = fmaf(a0, inv, s0.x), o1 = fmaf(a1, inv, s0.y);
        float o2 = fmaf(a2, inv, s0.z), o3 = fmaf(a3, inv, s0.w);
        float o4 = fmaf(a4, inv, s1.x), o5 = fmaf(a5, inv, s1.y);
        float o6 = fmaf(a6, inv, s1.z), o7 = fmaf(a7, inv, s1.w);
        if (RELU) {
            o0 = fmaxf(o0, 0.f); o1 = fmaxf(o1, 0.f); o2 = fmaxf(o2, 0.f); o3 = fmaxf(o3, 0.f);
            o4 = fmaxf(o4, 0.f); o5 = fmaxf(o5, 0.f); o6 = fmaxf(o6, 0.f); o7 = fmaxf(o7, 0.f);
        }
        if (H16OUT) {
            uint4 w;
            *(__half2*)&w.x = __floats2half2_rn(o0, o1);
            *(__half2*)&w.y = __floats2half2_rn(o2, o3);
            *(__half2*)&w.z = __floats2half2_rn(o4, o5);
            *(__half2*)&w.w = __floats2half2_rn(o6, o7);
            *(uint4*)(hout16 + base) = w;
        } else {
            *(float4*)&h[base]     = make_float4(o0, o1, o2, o3);
            *(float4*)&h[base + 4] = make_float4(o4, o5, o6, o7);
        }
    }
}

// ---------------- classifier: 16 threads per label edge, fp16 rows ----------------
__global__ __launch_bounds__(256) void k_classify(const int* __restrict__ lu,
                                                  const int* __restrict__ lp,
                                                  const __half* __restrict__ cu,
                                                  const __half* __restrict__ cp,
                                                  float* __restrict__ out) {
    int gid = blockIdx.x * blockDim.x + threadIdx.x;
    int e = gid >> 4;
    int l = gid & 15;
    if (e >= NLAB) return;
    int u = __ldg(&lu[e]);
    int p = __ldg(&lp[e]);
    uint2 ra = *(const uint2*)(cu + (size_t)u * 64 + l * 4);
    uint2 rb = *(const uint2*)(cp + (size_t)p * 64 + l * 4);
    float2 a0 = __half22float2(*(const __half2*)&ra.x);
    float2 a1 = __half22float2(*(const __half2*)&ra.y);
    float2 b0 = __half22float2(*(const __half2*)&rb.x);
    float2 b1 = __half22float2(*(const __half2*)&rb.y);
    float s = a0.x * b0.x + a0.y * b0.y + a1.x * b1.x + a1.y * b1.y;
    s += __shfl_xor_sync(0xffffffffu, s, 8);
    s += __shfl_xor_sync(0xffffffffu, s, 4);
    s += __shfl_xor_sync(0xffffffffu, s, 2);
    s += __shfl_xor_sync(0xffffffffu, s, 1);
    if (l == 0) out[e] = s;
}

// ---------------- launcher ----------------
extern "C" void kernel_launch(void* const* d_in, const int* in_sizes, int n_in,
                              void* d_out, int out_size) {
    const float* x_user    = (const float*)d_in[0];
    const float* x_product = (const float*)d_in[1];
    const float* W1_buys_l = (const float*)d_in[2];
    const float* b1_buys   = (const float*)d_in[3];
    const float* W1_buys_r = (const float*)d_in[4];
    const float* W1_rev_l  = (const float*)d_in[5];
    const float* b1_rev    = (const float*)d_in[6];
    const float* W1_rev_r  = (const float*)d_in[7];
    const float* W2_buys_l = (const float*)d_in[8];
    const float* b2_buys   = (const float*)d_in[9];
    const float* W2_buys_r = (const float*)d_in[10];
    const float* W2_rev_l  = (const float*)d_in[11];
    const float* b2_rev    = (const float*)d_in[12];
    const float* W2_rev_r  = (const float*)d_in[13];
    const int* edge_src = (const int*)d_in[14];
    const int* edge_dst = (const int*)d_in[15];
    const int* lab_u    = (const int*)d_in[16];
    const int* lab_p    = (const int*)d_in[17];
    float* out = (float*)d_out;

    static int init_done = 0;
    static int *deg_p, *deg_u, *off_p, *off_u, *cur_p, *cur_u;
    static int *csr_src, *csr_dst, *bsum_p, *bsum_u;
    static __half *tu, *tp, *tu2, *tp2, *cu, *cp;
    static float *hu, *hp, *hu2, *hp2;
    static cudaStream_t s1, s2;
    static cudaEvent_t ev[10];
    if (!init_done) {
        void* p;
        cudaGetSymbolAddress(&p, g_deg_p); deg_p = (int*)p;
        cudaGetSymbolAddress(&p, g_deg_u); deg_u = (int*)p;
        cudaGetSymbolAddress(&p, g_off_p); off_p = (int*)p;
        cudaGetSymbolAddress(&p, g_off_u); off_u = (int*)p;
        cudaGetSymbolAddress(&p, g_cur_p); cur_p = (int*)p;
        cudaGetSymbolAddress(&p, g_cur_u); cur_u = (int*)p;
        cudaGetSymbolAddress(&p, g_csr_src); csr_src = (int*)p;
        cudaGetSymbolAddress(&p, g_csr_dst); csr_dst = (int*)p;
        cudaGetSymbolAddress(&p, g_bsum_p); bsum_p = (int*)p;
        cudaGetSymbolAddress(&p, g_bsum_u); bsum_u = (int*)p;
        cudaGetSymbolAddress(&p, g_tu);  tu  = (__half*)p;
        cudaGetSymbolAddress(&p, g_tp);  tp  = (__half*)p;
        cudaGetSymbolAddress(&p, g_tu2); tu2 = (__half*)p;
        cudaGetSymbolAddress(&p, g_tp2); tp2 = (__half*)p;
        cudaGetSymbolAddress(&p, g_cu);  cu  = (__half*)p;
        cudaGetSymbolAddress(&p, g_cp);  cp  = (__half*)p;
        cudaGetSymbolAddress(&p, g_hu);  hu  = (float*)p;
        cudaGetSymbolAddress(&p, g_hp);  hp  = (float*)p;
        cudaGetSymbolAddress(&p, g_hu2); hu2 = (float*)p;
        cudaGetSymbolAddress(&p, g_hp2); hp2 = (float*)p;
        cudaFuncSetAttribute(k_gemm2<64>, cudaFuncAttributeMaxDynamicSharedMemorySize, 40960);
        cudaFuncSetAttribute(k_gemm2<128>, cudaFuncAttributeMaxDynamicSharedMemorySize, 81920);
        cudaStreamCreateWithFlags(&s1, cudaStreamNonBlocking);
        cudaStreamCreateWithFlags(&s2, cudaStreamNonBlocking);
        for (int i = 0; i < 10; i++) cudaEventCreateWithFlags(&ev[i], cudaEventDisableTiming);
        init_done = 1;
    }

    const int nb_p = (NP + 1023) / 1024;
    const int nb_u = (NU + 1023) / 1024;
    const int SM64 = 40960, SM128 = 81920;
    cudaStream_t s0 = 0;

    // ---- fork ----
    cudaEventRecord(ev[0], s0);
    cudaStreamWaitEvent(s1, ev[0], 0);
    cudaStreamWaitEvent(s2, ev[0], 0);

    // s1: p-side CSR
    k_zero_side<<<(NP + 255) / 256, 256, 0, s1>>>(deg_p, cur_p, NP);
    k_degree_side<<<(NE + 255) / 256, 256, 0, s1>>>(edge_dst, deg_p);
    k_scan1<<<nb_p, 1024, 0, s1>>>(deg_p, NP, off_p, bsum_p);
    k_scan2<<<1, 1024, 0, s1>>>(bsum_p, nb_p);
    k_scan3<<<nb_p, 1024, 0, s1>>>(off_p, NP, bsum_p);
    k_fill_side<<<(NE + 255) / 256, 256, 0, s1>>>(edge_dst, edge_src, off_p, cur_p, csr_src);

    // s2: u-side CSR
    k_zero_side<<<(NU + 255) / 256, 256, 0, s2>>>(deg_u, cur_u, NU);
    k_degree_side<<<(NE + 255) / 256, 256, 0, s2>>>(edge_src, deg_u);
    k_scan1<<<nb_u, 1024, 0, s2>>>(deg_u, NU, off_u, bsum_u);
    k_scan2<<<1, 1024, 0, s2>>>(bsum_u, nb_u);
    k_scan3<<<nb_u, 1024, 0, s2>>>(off_u, NU, bsum_u);
    k_fill_side<<<(NE + 255) / 256, 256, 0, s2>>>(edge_src, edge_dst, off_u, cur_u, csr_dst);

    // s0: layer-1 fused GEMMs
    k_gemm2<64><<<(NU + 31) / 32, 256, SM64, s0>>>(x_user, W1_buys_l, W1_rev_r, b1_rev, tu, hu, NU);
    k_gemm2<128><<<(NP + 31) / 32, 256, SM128, s0>>>(x_product, W1_rev_l, W1_buys_r, b1_buys, tp, hp, NP);
    cudaEventRecord(ev[1], s0);

    // layer-1 aggregation
    cudaStreamWaitEvent(s1, ev[1], 0);
    cudaStreamWaitEvent(s2, ev[1], 0);
    k_agg<true, false><<<(NP * 32 + 255) / 256, 256, 0, s1>>>(tu, csr_src, off_p, deg_p, hp, (__half*)0, NP);
    k_agg<true, false><<<(NU * 32 + 255) / 256, 256, 0, s2>>>(tp, csr_dst, off_u, deg_u, hu, (__half*)0, NU);

    // layer-2 GEMMs
    k_gemm2<64><<<(NP + 31) / 32, 256, SM64, s1>>>(hp, W2_rev_l, W2_buys_r, b2_buys, tp2, hp2, NP);
    k_gemm2<64><<<(NU + 31) / 32, 256, SM64, s2>>>(hu, W2_buys_l, W2_rev_r, b2_rev, tu2, hu2, NU);
    cudaEventRecord(ev[2], s1);   // hp2, tp2 ready
    cudaEventRecord(ev[3], s2);   // hu2, tu2 ready

    // layer-2 aggregation -> fp16 classifier rows
    cudaStreamWaitEvent(s1, ev[3], 0);
    cudaStreamWaitEvent(s2, ev[2], 0);
    k_agg<false, true><<<(NP * 32 + 255) / 256, 256, 0, s1>>>(tu2, csr_src, off_p, deg_p, hp2, cp, NP);
    k_agg<false, true><<<(NU * 32 + 255) / 256, 256, 0, s2>>>(tp2, csr_dst, off_u, deg_u, hu2, cu, NU);

    // ---- join, classify ----
    cudaEventRecord(ev[4], s1);
    cudaEventRecord(ev[5], s2);
    cudaStreamWaitEvent(s0, ev[4], 0);
    cudaStreamWaitEvent(s0, ev[5], 0);
    k_classify<<<(NLAB * 16 + 255) / 256, 256, 0, s0>>>(lab_u, lab_p, cu, cp, out);
}